// round 17
// baseline (speedup 1.0000x reference)
#include <cuda_runtime.h>
#include <cuda_fp16.h>
#include <cstdint>
#include <math.h>

// Problem dims
#define BB 4
#define TT 1024
#define CC 1024
#define HH 16
#define DD 64
#define FF 4096
#define MR 4096   // B*T

// ---------------------------------------------------------------------------
// Scratch (static device globals)
// ---------------------------------------------------------------------------
__device__ __align__(256) __half g_qkv[MR * 3 * CC];
__device__ __align__(256) __half g_h  [MR * CC];   // LN1 out; reused for proj fp16
__device__ __align__(256) __half g_at [MR * CC];
__device__ __align__(256) __half g_h2 [MR * CC];
__device__ __align__(256) __half g_f1 [MR * FF];
__device__ __align__(256) __half g_wq [3 * CC * CC];
__device__ __align__(256) __half g_wo [CC * CC];
__device__ __align__(256) __half g_w1 [FF * CC];
__device__ __align__(256) __half g_w2 [CC * FF];
__device__ int g_mask[MR];
__device__ int g_fu[BB];

// ---------------------------------------------------------------------------
// Helpers
// ---------------------------------------------------------------------------
__device__ __forceinline__ uint32_t smem_u32(const void* p) {
    uint32_t a;
    asm("{ .reg .u64 t; cvta.to.shared.u64 t, %1; cvt.u32.u64 %0, t; }" : "=r"(a) : "l"(p));
    return a;
}
__device__ __forceinline__ void cp16(uint32_t s, const void* g) {
    asm volatile("cp.async.cg.shared.global [%0], [%1], 16;" :: "r"(s), "l"(g));
}
#define CP_COMMIT() asm volatile("cp.async.commit_group;" ::: "memory")
#define CP_WAIT3()  asm volatile("cp.async.wait_group 3;"  ::: "memory")
#define CP_WAIT1()  asm volatile("cp.async.wait_group 1;"  ::: "memory")
#define CP_WAIT0()  asm volatile("cp.async.wait_group 0;"  ::: "memory")

#define LDSM4(r, addr) \
    asm volatile("ldmatrix.sync.aligned.m8n8.x4.shared.b16 {%0,%1,%2,%3}, [%4];" \
        : "=r"((r)[0]), "=r"((r)[1]), "=r"((r)[2]), "=r"((r)[3]) : "r"(addr))
#define LDSM4T(r, addr) \
    asm volatile("ldmatrix.sync.aligned.m8n8.x4.trans.shared.b16 {%0,%1,%2,%3}, [%4];" \
        : "=r"((r)[0]), "=r"((r)[1]), "=r"((r)[2]), "=r"((r)[3]) : "r"(addr))

__device__ __forceinline__ void mma16816(float* c, const uint32_t* a, const uint32_t* b) {
    asm volatile("mma.sync.aligned.m16n8k16.row.col.f32.f16.f16.f32 "
        "{%0,%1,%2,%3}, {%4,%5,%6,%7}, {%8,%9}, {%0,%1,%2,%3};"
        : "+f"(c[0]), "+f"(c[1]), "+f"(c[2]), "+f"(c[3])
        : "r"(a[0]), "r"(a[1]), "r"(a[2]), "r"(a[3]), "r"(b[0]), "r"(b[1]));
}

__device__ __forceinline__ float fex2(float x) {
    float r;
    asm("ex2.approx.ftz.f32 %0, %1;" : "=f"(r) : "f"(x));
    return r;
}

// ---------------------------------------------------------------------------
// g_fu init (runs before mask_expand on side stream)
// ---------------------------------------------------------------------------
__global__ void fu_init_kernel()
{
    if (threadIdx.x < BB) g_fu[threadIdx.x] = TT;
}

// ---------------------------------------------------------------------------
// Mask classify + expand + first-unpadded per batch (16 blocks)
// ---------------------------------------------------------------------------
__global__ void mask_expand_kernel(const void* __restrict__ pm, int* __restrict__ out)
{
    int tid = threadIdx.x;
    const unsigned* w = (const unsigned*)pm;
    int li = 0, lf = 0;
    for (int i = tid; i < 1024; i += 256) {
        unsigned v = w[i];
        li |= (v > 1u);
        lf |= (v != 0u && v != 0x3F800000u);
    }
    int not_int = __syncthreads_or(li);
    int not_flt = __syncthreads_or(lf);
    int cls = (!not_int) ? 0 : ((!not_flt) ? 1 : 2);
    int i = blockIdx.x * 256 + tid;
    int m;
    if (cls == 0)      m = (((const int*)pm)[i] != 0);
    else if (cls == 1) m = (((const float*)pm)[i] != 0.0f);
    else               m = (((const unsigned char*)pm)[i] != 0);
    out[i] = m;
    if (!m) atomicMin(&g_fu[i >> 10], i & 1023);
}

// ---------------------------------------------------------------------------
// Tiled pack of Wq/Wk/Wv (H,C,D) -> transposed (3C, C) fp16, coalesced.
// ---------------------------------------------------------------------------
__global__ void pack_qkv_kernel(const float* __restrict__ Wq,
                                const float* __restrict__ Wk,
                                const float* __restrict__ Wv,
                                __half* __restrict__ oh)
{
    __shared__ float t[32][65];
    int bid = blockIdx.x;
    int wsel = bid >> 9;
    int rem = bid & 511;
    int h = rem >> 5, ct = rem & 31;
    const float* W = (wsel == 0) ? Wq : (wsel == 1) ? Wk : Wv;
    int c0 = ct * 32;
    int x = threadIdx.x, y = threadIdx.y;   // 32 x 8

    const float* src = W + ((size_t)h * CC + c0) * DD;
#pragma unroll
    for (int i = 0; i < 4; i++) {
        int cc = y + i * 8;
        t[cc][x]      = src[(size_t)cc * DD + x];
        t[cc][x + 32] = src[(size_t)cc * DD + x + 32];
    }
    __syncthreads();

    size_t obase = ((size_t)wsel * CC + h * DD) * CC + c0;
#pragma unroll
    for (int i = 0; i < 8; i++) {
        int d = y + i * 8;
        oh[obase + (size_t)d * CC + x] = __float2half_rn(t[x][d]);
    }
}

// ---------------------------------------------------------------------------
// Tiled transpose: in (R, Cn) fp32 -> out (Cn, R) fp16
// ---------------------------------------------------------------------------
__global__ void tsplit_kernel(const float* __restrict__ in,
                              __half* __restrict__ oh,
                              int R, int Cn)
{
    __shared__ float t[32][33];
    int c0 = blockIdx.x * 32, r0 = blockIdx.y * 32;
    int x = threadIdx.x, y = threadIdx.y;
#pragma unroll
    for (int i = 0; i < 32; i += 8)
        t[y + i][x] = in[(size_t)(r0 + y + i) * Cn + c0 + x];
    __syncthreads();
#pragma unroll
    for (int i = 0; i < 32; i += 8)
        oh[(size_t)(c0 + y + i) * R + r0 + x] = __float2half_rn(t[x][y + i]);
}

// ---------------------------------------------------------------------------
// LayerNorm (fp32 input) -> fp16
// ---------------------------------------------------------------------------
__global__ __launch_bounds__(256) void ln_kernel(const float* __restrict__ x,
                                                 const float* __restrict__ g,
                                                 const float* __restrict__ b,
                                                 __half* __restrict__ oh)
{
    int row = blockIdx.x, tid = threadIdx.x;
    const float* xr = x + (size_t)row * CC;
    float v[4];
    float s = 0.f, ss = 0.f;
#pragma unroll
    for (int i = 0; i < 4; i++) {
        v[i] = xr[tid + i * 256];
        s += v[i];
        ss += v[i] * v[i];
    }
#pragma unroll
    for (int o = 16; o; o >>= 1) {
        s  += __shfl_xor_sync(0xffffffffu, s,  o);
        ss += __shfl_xor_sync(0xffffffffu, ss, o);
    }
    __shared__ float ws[8], wss[8];
    __shared__ float s_m, s_r;
    int wid = tid >> 5;
    if ((tid & 31) == 0) { ws[wid] = s; wss[wid] = ss; }
    __syncthreads();
    if (tid == 0) {
        float S = 0.f, SS = 0.f;
        for (int i = 0; i < 8; i++) { S += ws[i]; SS += wss[i]; }
        float m = S * (1.0f / CC);
        float var = SS * (1.0f / CC) - m * m;
        s_m = m;
        s_r = rsqrtf(var + 1e-5f);
    }
    __syncthreads();
    float m = s_m, r = s_r;
#pragma unroll
    for (int i = 0; i < 4; i++) {
        int c = tid + i * 256;
        float o = (v[i] - m) * r * g[c] + b[c];
        oh[(size_t)row * CC + c] = __float2half_rn(o);
    }
}

// ---------------------------------------------------------------------------
// LayerNorm (fp16 input) -> fp16
// ---------------------------------------------------------------------------
__global__ __launch_bounds__(256) void ln_h_kernel(const __half* __restrict__ x,
                                                   const float* __restrict__ g,
                                                   const float* __restrict__ b,
                                                   __half* __restrict__ oh)
{
    int row = blockIdx.x, tid = threadIdx.x;
    const __half* xr = x + (size_t)row * CC;
    float v[4];
    float s = 0.f, ss = 0.f;
#pragma unroll
    for (int i = 0; i < 4; i++) {
        v[i] = __half2float(xr[tid + i * 256]);
        s += v[i];
        ss += v[i] * v[i];
    }
#pragma unroll
    for (int o = 16; o; o >>= 1) {
        s  += __shfl_xor_sync(0xffffffffu, s,  o);
        ss += __shfl_xor_sync(0xffffffffu, ss, o);
    }
    __shared__ float ws[8], wss[8];
    __shared__ float s_m, s_r;
    int wid = tid >> 5;
    if ((tid & 31) == 0) { ws[wid] = s; wss[wid] = ss; }
    __syncthreads();
    if (tid == 0) {
        float S = 0.f, SS = 0.f;
        for (int i = 0; i < 8; i++) { S += ws[i]; SS += wss[i]; }
        float m = S * (1.0f / CC);
        float var = SS * (1.0f / CC) - m * m;
        s_m = m;
        s_r = rsqrtf(var + 1e-5f);
    }
    __syncthreads();
    float m = s_m, r = s_r;
#pragma unroll
    for (int i = 0; i < 4; i++) {
        int c = tid + i * 256;
        float o = (v[i] - m) * r * g[c] + b[c];
        oh[(size_t)row * CC + c] = __float2half_rn(o);
    }
}

// ---------------------------------------------------------------------------
// fp16 1-pass GEMM (validated R14 config, untouched)
// ---------------------------------------------------------------------------
#define PITCH 72
#define A_TILE_B (128 * PITCH * 2)
#define B_TILE_B (256 * PITCH * 2)
#define STAGE_B (A_TILE_B + B_TILE_B)
#define NSTAGE 4
#define GEMM_SMEM (NSTAGE * STAGE_B)

__global__ __launch_bounds__(256, 1) void gemm_mma(
    const __half* __restrict__ Ah,
    const __half* __restrict__ Bh,
    const float* __restrict__ bias,
    float* __restrict__ outF,
    __half* __restrict__ outH,
    int Ntot, int Ktot, int relu)
{
    extern __shared__ __align__(128) char smem[];
    const uint32_t sb0 = smem_u32(smem);
    int tid = threadIdx.x, lane = tid & 31, w = tid >> 5;
    int bm = blockIdx.y * 128, bn = blockIdx.x * 256;
    int wm = (w & 1) * 64, wn = (w >> 1) * 64;
    int nk = Ktot >> 6;

    float acc[4][8][4];
#pragma unroll
    for (int i = 0; i < 4; i++)
#pragma unroll
        for (int j = 0; j < 8; j++)
#pragma unroll
            for (int e = 0; e < 4; e++) acc[i][j][e] = 0.0f;

    auto load_stage = [&](int st, int kc) {
        uint32_t sb = sb0 + st * STAGE_B;
#pragma unroll
        for (int i = 0; i < 12; i++) {
            int idx = tid + i * 256;
            int c = (idx & 7) * 8;
            if (idx < 1024) {
                int r = idx >> 3;
                cp16(sb + (uint32_t)(r * PITCH + c) * 2,
                     Ah + (size_t)(bm + r) * Ktot + kc + c);
            } else {
                int r = (idx - 1024) >> 3;
                cp16(sb + A_TILE_B + (uint32_t)(r * PITCH + c) * 2,
                     Bh + (size_t)(bn + r) * Ktot + kc + c);
            }
        }
    };

    load_stage(0, 0);  CP_COMMIT();
    load_stage(1, 64); CP_COMMIT();
    load_stage(2, 128); CP_COMMIT();

    int lrow = lane & 15;
    int lk = (lane >> 4) * 8;

    for (int kc = 0; kc < nk; kc++) {
        if (kc + 3 < nk) {
            load_stage((kc + 3) & 3, (kc + 3) * 64);
            CP_COMMIT();
            CP_WAIT3();
        } else {
            CP_WAIT0();
        }
        __syncthreads();

        uint32_t sb = sb0 + (kc & 3) * STAGE_B;
#pragma unroll
        for (int ks = 0; ks < 4; ks++) {
            int k0 = ks * 16;
            uint32_t ah[4][4], bh[8][2];
#pragma unroll
            for (int i = 0; i < 4; i++) {
                uint32_t ad = sb + (uint32_t)((wm + i * 16 + lrow) * PITCH + k0 + lk) * 2;
                LDSM4(ah[i], ad);
            }
#pragma unroll
            for (int jj = 0; jj < 4; jj++) {
                uint32_t bd = sb + A_TILE_B +
                              (uint32_t)((wn + jj * 16 + lrow) * PITCH + k0 + lk) * 2;
                uint32_t t[4];
                LDSM4(t, bd);
                bh[jj * 2][0] = t[0]; bh[jj * 2][1] = t[2];
                bh[jj * 2 + 1][0] = t[1]; bh[jj * 2 + 1][1] = t[3];
            }
#pragma unroll
            for (int i = 0; i < 4; i++)
#pragma unroll
                for (int j = 0; j < 8; j++)
                    mma16816(acc[i][j], ah[i], bh[j]);
        }
        __syncthreads();
    }

#pragma unroll
    for (int i = 0; i < 4; i++) {
        int r0 = bm + wm + i * 16 + (lane >> 2);
#pragma unroll
        for (int j = 0; j < 8; j++) {
            int c = bn + wn + j * 8 + (lane & 3) * 2;
            float bx0 = bias ? bias[c] : 0.0f;
            float bx1 = bias ? bias[c + 1] : 0.0f;
#pragma unroll
            for (int hh = 0; hh < 2; hh++) {
                int r = r0 + hh * 8;
                float v0 = acc[i][j][hh * 2 + 0] + bx0;
                float v1 = acc[i][j][hh * 2 + 1] + bx1;
                if (relu) { v0 = fmaxf(v0, 0.0f); v1 = fmaxf(v1, 0.0f); }
                size_t o = (size_t)r * Ntot + c;
                if (outF) {
                    outF[o] = v0;
                    outF[o + 1] = v1;
                } else {
                    *(__half2*)(outH + o) = __floats2half2_rn(v0, v1);
                }
            }
        }
    }
}

// ---------------------------------------------------------------------------
// fp16 flash attention: single-pass QK, single-pass PV.
// CTA 512 thr (16 warps), q-tile 256 (16 rows/warp), K/V staged in 128-row
// chunks (double-buffered), two 64-column compute passes per stage.
// Causal-only sweep; heavy blocks first.
// ---------------------------------------------------------------------------
#define AT_PITCH 72
#define AQ_TILEB (256 * AT_PITCH * 2)       // 36864 (256 q rows)
#define AKV_TILEB (128 * AT_PITCH * 2)      // 36864 (128-row stage, K or V)
#define SMASK_OFF (AQ_TILEB + 4 * AKV_TILEB)       // 184320
#define ATT_SMEM (SMASK_OFF + 2 * 128 * 4)         // 185344

__global__ __launch_bounds__(512) void attn_mma(
    const __half* __restrict__ qkv,
    const int* __restrict__ mask,
    __half* __restrict__ outp)
{
    extern __shared__ __align__(128) char smem[];
    const uint32_t sb = smem_u32(smem);
    const uint32_t sQ = sb;

    int qi = (int)gridDim.x - 1 - (int)blockIdx.x;   // heavy blocks first
    int bh = blockIdx.y;
    int b = bh >> 4, h = bh & 15;
    int tid = threadIdx.x, lane = tid & 31, w = tid >> 5;
    int wq = w * 16;                                  // 16 warps x 16 rows = 256
    int lrow = lane & 15, lkc = (lane >> 4) * 8;

    const size_t rowbase = (size_t)(b * TT) * (3 * CC) + h * DD;
    const int* gmask = mask + b * TT;
    int* smask = (int*)(smem + SMASK_OFF);

    // Q tile: 256 rows x 64 cols fp16 (2048 cp16 over 512 threads)
#pragma unroll
    for (int i = 0; i < 4; i++) {
        int idx = tid + i * 512;
        int r = idx >> 3, ch = (idx & 7) * 8;
        uint32_t so = (uint32_t)(r * AT_PITCH + ch) * 2;
        size_t go = rowbase + (size_t)(qi * 256 + r) * (3 * CC) + ch;
        cp16(sQ + so, qkv + go);
    }

    // stage loader: 128 rows of K + 128 rows of V + 128 mask ints
    auto load_stage = [&](int sj) {
        int st = sj & 1;
        uint32_t base = sb + AQ_TILEB + st * (2 * AKV_TILEB);
#pragma unroll
        for (int i = 0; i < 4; i++) {
            int idx = tid + i * 512;          // 0..2047
            int tile = idx >> 10;             // 0:K 1:V
            int rem = idx & 1023;
            int r = rem >> 3, ch = (rem & 7) * 8;
            uint32_t so = base + tile * AKV_TILEB + (uint32_t)(r * AT_PITCH + ch) * 2;
            size_t gk = rowbase + (size_t)(sj * 128 + r) * (3 * CC) + CC + ch;
            if (tile == 0) cp16(so, qkv + gk);
            else           cp16(so, qkv + gk + CC);
        }
        if (tid < 32)
            cp16(sb + SMASK_OFF + st * 512 + tid * 16, gmask + sj * 128 + tid * 4);
    };

    int ns = 2 * qi + 2;
    load_stage(0);
    CP_COMMIT();

    float O[8][4];
#pragma unroll
    for (int j = 0; j < 8; j++)
#pragma unroll
        for (int e = 0; e < 4; e++) O[j][e] = 0.0f;
    float lsum0 = 0.0f, lsum1 = 0.0f;

    const float csc = 0.0450842200f;   // log2(e) / 32
    const int t_base = qi * 256 + wq + (lane >> 2);

    for (int sj = 0; sj < ns; sj++) {
        int cur = sj & 1;
        if (sj + 1 < ns) {
            load_stage(sj + 1);
            CP_COMMIT();
            CP_WAIT1();
        } else {
            CP_WAIT0();
        }
        __syncthreads();

        uint32_t kvb = sb + AQ_TILEB + cur * (2 * AKV_TILEB);
        const int* mrow = smask + cur * 128;

        // two 64-column halves per 128-row stage
#pragma unroll
        for (int half = 0; half < 2; half++) {
            uint32_t sK = kvb + (uint32_t)(half * 64) * AT_PITCH * 2;
            uint32_t sV = kvb + AKV_TILEB + (uint32_t)(half * 64) * AT_PITCH * 2;
            const int* mh_ = mrow + half * 64;
            int scol0 = sj * 128 + half * 64;

            // S = Q K^T
            float S[8][4];
#pragma unroll
            for (int j = 0; j < 8; j++)
#pragma unroll
                for (int e = 0; e < 4; e++) S[j][e] = 0.0f;

#pragma unroll
            for (int ks = 0; ks < 4; ks++) {
                uint32_t qa[4];
                uint32_t ad = sQ + (uint32_t)((wq + lrow) * AT_PITCH + ks * 16 + lkc) * 2;
                LDSM4(qa, ad);
#pragma unroll
                for (int nj = 0; nj < 4; nj++) {
                    uint32_t bd = sK + (uint32_t)((nj * 16 + lrow) * AT_PITCH + ks * 16 + lkc) * 2;
                    uint32_t th[4];
                    LDSM4(th, bd);
                    uint32_t bh0[2] = {th[0], th[2]}, bh1[2] = {th[1], th[3]};
                    mma16816(S[2 * nj],     qa, bh0);
                    mma16816(S[2 * nj + 1], qa, bh1);
                }
            }

            // mask + exp2 + pack P
            uint32_t aP[8][2];
#pragma unroll
            for (int j = 0; j < 8; j++) {
                int s0 = j * 8 + (lane & 3) * 2;
#pragma unroll
                for (int e = 0; e < 4; e++) {
                    int s_l = s0 + (e & 1);
                    int s_g = scol0 + s_l;
                    int t_g = t_base + (e >> 1) * 8;
                    float v = S[j][e] * csc;
                    if (mh_[s_l] || (s_g > t_g)) v = -1e9f;
                    S[j][e] = fex2(v);
                }
                lsum0 += S[j][0] + S[j][1];
                lsum1 += S[j][2] + S[j][3];
                __half2 h0 = __floats2half2_rn(S[j][0], S[j][1]);
                __half2 h1 = __floats2half2_rn(S[j][2], S[j][3]);
                aP[j][0] = *(uint32_t*)&h0;
                aP[j][1] = *(uint32_t*)&h1;
            }

            // O += P V
#pragma unroll
            for (int kc = 0; kc < 4; kc++) {
                uint32_t Af[4] = {aP[2 * kc][0], aP[2 * kc][1],
                                  aP[2 * kc + 1][0], aP[2 * kc + 1][1]};
#pragma unroll
                for (int dj = 0; dj < 4; dj++) {
                    uint32_t vd = sV + (uint32_t)((kc * 16 + lrow) * AT_PITCH + dj * 16 + lkc) * 2;
                    uint32_t tv[4];
                    LDSM4T(tv, vd);
                    uint32_t b0[2] = {tv[0], tv[1]}, b1[2] = {tv[2], tv[3]};
                    mma16816(O[2 * dj],     Af, b0);
                    mma16816(O[2 * dj + 1], Af, b1);
                }
            }
        }
        __syncthreads();
    }

    // finalize
    lsum0 += __shfl_xor_sync(0xffffffffu, lsum0, 1);
    lsum0 += __shfl_xor_sync(0xffffffffu, lsum0, 2);
    lsum1 += __shfl_xor_sync(0xffffffffu, lsum1, 1);
    lsum1 += __shfl_xor_sync(0xffffffffu, lsum1, 2);
    float inv0 = 1.0f / lsum0;
    float inv1 = 1.0f / lsum1;

#pragma unroll
    for (int hh = 0; hh < 2; hh++) {
        float inv = hh ? inv1 : inv0;
        size_t orow = (size_t)(b * TT + t_base + hh * 8) * CC + h * DD + (lane & 3) * 2;
#pragma unroll
        for (int j = 0; j < 8; j++) {
            float v0 = O[j][hh * 2 + 0] * inv;
            float v1 = O[j][hh * 2 + 1] * inv;
            *(__half2*)(outp + orow + j * 8) = __floats2half2_rn(v0, v1);
        }
    }
}

// ---------------------------------------------------------------------------
// Fixup: rows t < first_unpadded[b] -> out = mean of V over padded positions.
// ---------------------------------------------------------------------------
__global__ __launch_bounds__(256) void fixup_kernel(
    const __half* __restrict__ qkv,
    const int* __restrict__ mask,
    __half* __restrict__ outp)
{
    int b = blockIdx.x;
    int f = g_fu[b];
    if (f == 0) return;
    int tid = threadIdx.x;
    float sum[4] = {0, 0, 0, 0};
    int cnt = 0;
    for (int s = 0; s < TT; s++) {
        if (mask[b * TT + s]) {
            cnt++;
            size_t base = (size_t)(b * TT + s) * (3 * CC) + 2 * CC + tid * 4;
#pragma unroll
            for (int e = 0; e < 4; e++)
                sum[e] += __half2float(qkv[base + e]);
        }
    }
    float invc = 1.0f / (float)cnt;
    __half mh[4];
#pragma unroll
    for (int e = 0; e < 4; e++) mh[e] = __float2half_rn(sum[e] * invc);
    for (int t = 0; t < f; t++) {
        size_t o = (size_t)(b * TT + t) * CC + tid * 4;
#pragma unroll
        for (int e = 0; e < 4; e++)
            outp[o + e] = mh[e];
    }
}

// ---------------------------------------------------------------------------
// Launch. Side stream: mask + weight transposes, overlapped with LN1/QKV.
// ---------------------------------------------------------------------------
static cudaStream_t s_side = nullptr;
static cudaEvent_t  s_evF = nullptr, s_evM = nullptr, s_evJ = nullptr;

extern "C" void kernel_launch(void* const* d_in, const int* in_sizes, int n_in,
                              void* d_out, int out_size)
{
    const float* x     = (const float*)d_in[0];
    const void*  pmask = d_in[1];
    const float* Wq    = (const float*)d_in[2];
    const float* Wk    = (const float*)d_in[3];
    const float* Wv    = (const float*)d_in[4];
    const float* Wo    = (const float*)d_in[5];
    const float* bo    = (const float*)d_in[6];
    const float* ln1_g = (const float*)d_in[7];
    const float* ln1_b = (const float*)d_in[8];
    const float* ln2_g = (const float*)d_in[9];
    const float* ln2_b = (const float*)d_in[10];
    const float* W1    = (const float*)d_in[11];
    const float* b1    = (const float*)d_in[12];
    const float* W2    = (const float*)d_in[13];
    const float* b2    = (const float*)d_in[14];
    float* out = (float*)d_out;

    void *p_qkv, *p_h, *p_at, *p_h2, *p_f1,
         *p_wq, *p_wo, *p_w1, *p_w2, *p_mask;
    cudaGetSymbolAddress(&p_qkv,  g_qkv);
    cudaGetSymbolAddress(&p_h,    g_h);
    cudaGetSymbolAddress(&p_at,   g_at);
    cudaGetSymbolAddress(&p_h2,   g_h2);
    cudaGetSymbolAddress(&p_f1,   g_f1);
    cudaGetSymbolAddress(&p_wq,   g_wq);
    cudaGetSymbolAddress(&p_wo,   g_wo);
    cudaGetSymbolAddress(&p_w1,   g_w1);
    cudaGetSymbolAddress(&p_w2,   g_w2);
    cudaGetSymbolAddress(&p_mask, g_mask);

    cudaFuncSetAttribute(gemm_mma, cudaFuncAttributeMaxDynamicSharedMemorySize, GEMM_SMEM);
    cudaFuncSetAttribute(attn_mma, cudaFuncAttributeMaxDynamicSharedMemorySize, ATT_SMEM);

    if (!s_side) {
        cudaStreamCreateWithFlags(&s_side, cudaStreamNonBlocking);
        cudaEventCreateWithFlags(&s_evF, cudaEventDisableTiming);
        cudaEventCreateWithFlags(&s_evM, cudaEventDisableTiming);
        cudaEventCreateWithFlags(&s_evJ, cudaEventDisableTiming);
    }

    // ---- fork: mask + weight transposes on the side stream ----
    cudaEventRecord(s_evF, 0);
    cudaStreamWaitEvent(s_side, s_evF, 0);
    fu_init_kernel<<<1, 32, 0, s_side>>>();
    mask_expand_kernel<<<16, 256, 0, s_side>>>(pmask, (int*)p_mask);
    cudaEventRecord(s_evM, s_side);          // mask ready
    tsplit_kernel<<<dim3(CC / 32, CC / 32), dim3(32, 8), 0, s_side>>>(
        Wo, (__half*)p_wo, CC, CC);
    tsplit_kernel<<<dim3(FF / 32, CC / 32), dim3(32, 8), 0, s_side>>>(
        W1, (__half*)p_w1, CC, FF);
    tsplit_kernel<<<dim3(CC / 32, FF / 32), dim3(32, 8), 0, s_side>>>(
        W2, (__half*)p_w2, FF, CC);
    cudaEventRecord(s_evJ, s_side);          // weights ready

    // ---- main stream ----
    pack_qkv_kernel<<<3 * 16 * 32, dim3(32, 8)>>>(Wq, Wk, Wv, (__half*)p_wq);
    ln_kernel<<<MR, 256>>>(x, ln1_g, ln1_b, (__half*)p_h);
    gemm_mma<<<dim3(3 * CC / 256, MR / 128), 256, GEMM_SMEM>>>(
        (__half*)p_h, (__half*)p_wq, nullptr,
        nullptr, (__half*)p_qkv, 3 * CC, CC, 0);

    cudaStreamWaitEvent(0, s_evM, 0);        // mask ready before attention
    attn_mma<<<dim3(TT / 256, BB * HH), 512, ATT_SMEM>>>(
        (const __half*)p_qkv, (const int*)p_mask, (__half*)p_at);
    fixup_kernel<<<BB, 256>>>(
        (const __half*)p_qkv, (const int*)p_mask, (__half*)p_at);

    cudaStreamWaitEvent(0, s_evJ, 0);        // weights ready before Wo/FFN

    // Wo projection (fp16 out, reusing g_h)
    gemm_mma<<<dim3(CC / 256, MR / 128), 256, GEMM_SMEM>>>(
        (__half*)p_at, (__half*)p_wo, bo,
        nullptr, (__half*)p_h, CC, CC, 0);
    // LN2 (fp16 input)
    ln_h_kernel<<<MR, 256>>>((const __half*)p_h, ln2_g, ln2_b, (__half*)p_h2);
    // FFN1 + relu
    gemm_mma<<<dim3(FF / 256, MR / 128), 256, GEMM_SMEM>>>(
        (__half*)p_h2, (__half*)p_w1, b1,
        nullptr, (__half*)p_f1, FF, CC, 1);
    // FFN2 -> d_out
    gemm_mma<<<dim3(CC / 256, MR / 128), 256, GEMM_SMEM>>>(
        (__half*)p_f1, (__half*)p_w2, b2,
        out, nullptr, CC, FF, 0);
}